// round 1
// baseline (speedup 1.0000x reference)
#include <cuda_runtime.h>
#include <math.h>

#define BB    4
#define TSEQ  2048
#define DM    1024
#define DI    2048
#define DS_   16
#define DTR   64
#define FFND  3584
#define MROWS (BB*TSEQ)   // 8192
#define NC    64          // scan chunks
#define CL    32          // chunk length (NC*CL == TSEQ)

// ---------------- static device scratch (no allocations allowed) ----------
__device__ float g_X  [MROWS*DM];        // residual stream
__device__ float g_Xn [MROWS*DM];        // layernorm output
__device__ float g_xz [MROWS*2*DI];      // in_proj output
__device__ float g_xc [MROWS*DI];        // conv+silu output
__device__ float g_xd [MROWS*96];        // x_proj output (dt|B|C)
__device__ float g_dt [MROWS*DI];        // softplus(dt)
__device__ float g_ym [MROWS*DI];        // gated scan output
__device__ float g_ffn[MROWS*FFND];      // ffn hidden
__device__ float g_cP [BB*NC*DI*DS_];    // chunk transition products
__device__ float g_cS [BB*NC*DI*DS_];    // chunk partial states
__device__ float g_cI [BB*NC*DI*DS_];    // chunk incoming states

// ---------------- positional encoding + input copy ------------------------
__global__ void k_add_pe(const float* __restrict__ xin, float* __restrict__ X) {
    int idx = blockIdx.x * 256 + threadIdx.x;      // over MROWS*DM
    int d = idx & (DM - 1);
    int m = idx >> 10;
    int t = m & (TSEQ - 1);
    int p2 = d & ~1;
    float freq = expf((float)p2 * (-9.210340371976184f / (float)DM));
    float ang = (float)t * freq;
    float pe = (d & 1) ? cosf(ang) : sinf(ang);
    X[idx] = xin[idx] + pe;
}

// ---------------- layernorm (1024 cols, 256 thr, 1 float4/thr) ------------
__device__ __forceinline__ float blockReduce(float v, float* sh) {
    int lane = threadIdx.x & 31, wid = threadIdx.x >> 5;
    #pragma unroll
    for (int o = 16; o > 0; o >>= 1) v += __shfl_down_sync(0xffffffffu, v, o);
    if (lane == 0) sh[wid] = v;
    __syncthreads();
    if (threadIdx.x == 0) {
        float s = 0.f;
        #pragma unroll
        for (int i = 0; i < 8; i++) s += sh[i];
        sh[32] = s;
    }
    __syncthreads();
    float r = sh[32];
    __syncthreads();
    return r;
}

__global__ __launch_bounds__(256) void k_ln(const float* __restrict__ in,
                                            float* __restrict__ out,
                                            const float* __restrict__ g,
                                            const float* __restrict__ b) {
    __shared__ float sh[33];
    int row = blockIdx.x;
    float4 v = ((const float4*)(in + (size_t)row * DM))[threadIdx.x];
    float mean = blockReduce(v.x + v.y + v.z + v.w, sh) * (1.0f / DM);
    float dx = v.x - mean, dy = v.y - mean, dz = v.z - mean, dw = v.w - mean;
    float var = blockReduce(dx*dx + dy*dy + dz*dz + dw*dw, sh) * (1.0f / DM);
    float rstd = rsqrtf(var + 1e-5f);
    int c = threadIdx.x * 4;
    float4 o;
    o.x = dx * rstd * g[c + 0] + b[c + 0];
    o.y = dy * rstd * g[c + 1] + b[c + 1];
    o.z = dz * rstd * g[c + 2] + b[c + 2];
    o.w = dw * rstd * g[c + 3] + b[c + 3];
    ((float4*)(out + (size_t)row * DM))[threadIdx.x] = o;
}

// ---------------- generic SGEMM: C[m,n] = sum_k A[m,k] * W[n,k] -----------
// epi: 0:C=acc  1:+bias  2:gelu(acc+bias)  3:C+=acc  4:C+=acc+bias  5:softplus(acc+bias)
__global__ __launch_bounds__(256) void k_gemm(
    const float* __restrict__ A, const float* __restrict__ W,
    float* __restrict__ C, const float* __restrict__ bias,
    int Mr, int N, int K, int lda, int ldw, int ldc, int epi) {
    __shared__ float As[8][132];
    __shared__ float Bs[8][132];
    int tid = threadIdx.x;
    int tx = tid & 15, ty = tid >> 4;
    int bM = blockIdx.y * 128;
    int bN = blockIdx.x * 128;
    int lrow = tid >> 1;
    int lcol = (tid & 1) << 2;
    const float* Aptr = A + (size_t)(bM + lrow) * lda + lcol;
    const float* Wptr = W + (size_t)(bN + lrow) * ldw + lcol;
    bool aval = (bM + lrow) < Mr;
    bool wval = (bN + lrow) < N;

    float acc[8][8];
    #pragma unroll
    for (int i = 0; i < 8; i++)
        #pragma unroll
        for (int j = 0; j < 8; j++) acc[i][j] = 0.f;

    for (int k0 = 0; k0 < K; k0 += 8) {
        float4 av = make_float4(0.f, 0.f, 0.f, 0.f);
        float4 wv = make_float4(0.f, 0.f, 0.f, 0.f);
        if (aval) av = *(const float4*)(Aptr + k0);
        if (wval) wv = *(const float4*)(Wptr + k0);
        __syncthreads();
        As[lcol + 0][lrow] = av.x; As[lcol + 1][lrow] = av.y;
        As[lcol + 2][lrow] = av.z; As[lcol + 3][lrow] = av.w;
        Bs[lcol + 0][lrow] = wv.x; Bs[lcol + 1][lrow] = wv.y;
        Bs[lcol + 2][lrow] = wv.z; Bs[lcol + 3][lrow] = wv.w;
        __syncthreads();
        #pragma unroll
        for (int kk = 0; kk < 8; kk++) {
            float ra[8], rb[8];
            #pragma unroll
            for (int i = 0; i < 8; i++) ra[i] = As[kk][ty * 8 + i];
            #pragma unroll
            for (int j = 0; j < 8; j++) rb[j] = Bs[kk][tx * 8 + j];
            #pragma unroll
            for (int i = 0; i < 8; i++)
                #pragma unroll
                for (int j = 0; j < 8; j++) acc[i][j] += ra[i] * rb[j];
        }
    }

    #pragma unroll
    for (int i = 0; i < 8; i++) {
        int r = bM + ty * 8 + i;
        if (r >= Mr) continue;
        #pragma unroll
        for (int j = 0; j < 8; j++) {
            int cn = bN + tx * 8 + j;
            if (cn >= N) continue;
            float v = acc[i][j];
            float* cp = C + (size_t)r * ldc + cn;
            if (epi == 0) { *cp = v; }
            else if (epi == 1) { *cp = v + bias[cn]; }
            else if (epi == 2) {
                float u = v + bias[cn];
                *cp = 0.5f * u * (1.0f + erff(u * 0.70710678118654752f));
            } else if (epi == 3) { *cp = *cp + v; }
            else if (epi == 4) { *cp = *cp + v + bias[cn]; }
            else { // 5: softplus
                float u = v + bias[cn];
                *cp = (u > 20.f) ? u : log1pf(expf(u));
            }
        }
    }
}

// ---------------- causal depthwise conv (k=4) + silu ----------------------
__global__ void k_conv(const float* __restrict__ xz, const float* __restrict__ cw,
                       const float* __restrict__ cb, float* __restrict__ xc) {
    int idx = blockIdx.x * 256 + threadIdx.x;   // over MROWS*DI
    int d = idx & (DI - 1);
    int m = idx >> 11;
    int t = m & (TSEQ - 1);
    float acc = cb[d];
    #pragma unroll
    for (int k = 0; k < 4; k++) {
        int tt = t + k - 3;
        if (tt >= 0) acc += xz[(size_t)(m + k - 3) * (2 * DI) + d] * cw[d * 4 + k];
    }
    float sg = 1.0f / (1.0f + expf(-acc));
    xc[idx] = acc * sg;
}

// ---------------- scan pass A: per-chunk transition + partial state -------
__global__ __launch_bounds__(256) void k_scanA(
    const float* __restrict__ dt, const float* __restrict__ xc,
    const float* __restrict__ xd, const float* __restrict__ Alog,
    float* __restrict__ gP, float* __restrict__ gS) {
    __shared__ float shB[CL][DS_];
    int b = blockIdx.z, c = blockIdx.y;
    int d = blockIdx.x * 256 + threadIdx.x;
    int mbase = b * TSEQ + c * CL;
    for (int idx = threadIdx.x; idx < CL * DS_; idx += 256) {
        int t = idx >> 4, col = idx & 15;
        shB[t][col] = xd[(size_t)(mbase + t) * 96 + 64 + col];
    }
    __syncthreads();
    float r[DS_];
    bool fast = true;
    #pragma unroll
    for (int n = 0; n < DS_; n++) {
        r[n] = expf(Alog[(size_t)d * DS_ + n]);
        fast = fast && (fabsf(r[n] - (float)(n + 1)) < 1e-3f * (float)(n + 1));
    }
    float P[DS_], S[DS_];
    #pragma unroll
    for (int n = 0; n < DS_; n++) { P[n] = 1.f; S[n] = 0.f; }
    for (int t = 0; t < CL; t++) {
        int m = mbase + t;
        float dv = dt[(size_t)m * DI + d];
        float xv = xc[(size_t)m * DI + d];
        float u = xv * dv;
        float dA[DS_];
        if (fast) {
            float e = expf(-dv);
            float p = 1.f;
            #pragma unroll
            for (int n = 0; n < DS_; n++) { p *= e; dA[n] = p; }
        } else {
            #pragma unroll
            for (int n = 0; n < DS_; n++) dA[n] = expf(-dv * r[n]);
        }
        #pragma unroll
        for (int n = 0; n < DS_; n++) {
            S[n] = S[n] * dA[n] + u * shB[t][n];
            P[n] *= dA[n];
        }
    }
    size_t base = (((size_t)b * NC + c) * DI + d) * DS_;
    #pragma unroll
    for (int n = 0; n < DS_; n += 4) {
        *(float4*)(gP + base + n) = make_float4(P[n], P[n+1], P[n+2], P[n+3]);
        *(float4*)(gS + base + n) = make_float4(S[n], S[n+1], S[n+2], S[n+3]);
    }
}

// ---------------- scan pass B: sequential chunk combine -------------------
__global__ void k_scanB(const float* __restrict__ gP, const float* __restrict__ gS,
                        float* __restrict__ gI) {
    int idx = blockIdx.x * 256 + threadIdx.x;   // b*DI + d, 8192 total
    int b = idx >> 11, d = idx & (DI - 1);
    float s[DS_];
    #pragma unroll
    for (int n = 0; n < DS_; n++) s[n] = 0.f;
    for (int c = 0; c < NC; c++) {
        size_t base = (((size_t)b * NC + c) * DI + d) * DS_;
        #pragma unroll
        for (int n = 0; n < DS_; n += 4)
            *(float4*)(gI + base + n) = make_float4(s[n], s[n+1], s[n+2], s[n+3]);
        #pragma unroll
        for (int n = 0; n < DS_; n += 4) {
            float4 P = *(const float4*)(gP + base + n);
            float4 S = *(const float4*)(gS + base + n);
            s[n+0] = s[n+0] * P.x + S.x;
            s[n+1] = s[n+1] * P.y + S.y;
            s[n+2] = s[n+2] * P.z + S.z;
            s[n+3] = s[n+3] * P.w + S.w;
        }
    }
}

// ---------------- scan pass C: replay with init state, emit gated output --
__global__ __launch_bounds__(256) void k_scanC(
    const float* __restrict__ dt, const float* __restrict__ xc,
    const float* __restrict__ xd, const float* __restrict__ xz,
    const float* __restrict__ Alog, const float* __restrict__ Dsk,
    const float* __restrict__ gI, float* __restrict__ ym) {
    __shared__ float shB[CL][DS_];
    __shared__ float shC[CL][DS_];
    int b = blockIdx.z, c = blockIdx.y;
    int d = blockIdx.x * 256 + threadIdx.x;
    int mbase = b * TSEQ + c * CL;
    for (int idx = threadIdx.x; idx < CL * 32; idx += 256) {
        int t = idx >> 5, col = idx & 31;
        float v = xd[(size_t)(mbase + t) * 96 + 64 + col];
        if (col < 16) shB[t][col] = v;
        else shC[t][col - 16] = v;
    }
    __syncthreads();
    float r[DS_];
    bool fast = true;
    #pragma unroll
    for (int n = 0; n < DS_; n++) {
        r[n] = expf(Alog[(size_t)d * DS_ + n]);
        fast = fast && (fabsf(r[n] - (float)(n + 1)) < 1e-3f * (float)(n + 1));
    }
    float dskip = Dsk[d];
    float s[DS_];
    size_t base = (((size_t)b * NC + c) * DI + d) * DS_;
    #pragma unroll
    for (int n = 0; n < DS_; n += 4) {
        float4 v = *(const float4*)(gI + base + n);
        s[n+0] = v.x; s[n+1] = v.y; s[n+2] = v.z; s[n+3] = v.w;
    }
    for (int t = 0; t < CL; t++) {
        int m = mbase + t;
        float dv = dt[(size_t)m * DI + d];
        float xv = xc[(size_t)m * DI + d];
        float u = xv * dv;
        float dA[DS_];
        if (fast) {
            float e = expf(-dv);
            float p = 1.f;
            #pragma unroll
            for (int n = 0; n < DS_; n++) { p *= e; dA[n] = p; }
        } else {
            #pragma unroll
            for (int n = 0; n < DS_; n++) dA[n] = expf(-dv * r[n]);
        }
        float y = 0.f;
        #pragma unroll
        for (int n = 0; n < DS_; n++) {
            s[n] = s[n] * dA[n] + u * shB[t][n];
            y += s[n] * shC[t][n];
        }
        float z = xz[(size_t)m * (2 * DI) + DI + d];
        float sg = 1.0f / (1.0f + expf(-z));
        ym[(size_t)m * DI + d] = (y + dskip * xv) * (z * sg);
    }
}

// ---------------- mask (+ optional write to output) -----------------------
__global__ void k_mask(float* __restrict__ X, const int* __restrict__ len,
                       float* __restrict__ out2) {
    int idx = blockIdx.x * 256 + threadIdx.x;   // over MROWS*DM
    int m = idx >> 10;
    int b = m >> 11;
    int t = m & (TSEQ - 1);
    float v = X[idx];
    v = (t < len[b]) ? v : 0.f;
    X[idx] = v;
    if (out2) out2[idx] = v;
}

// ---------------- host orchestration --------------------------------------
static void launch_gemm(const float* A, const float* W, float* C, const float* bias,
                        int Mr, int N, int K, int lda, int ldw, int ldc, int epi) {
    dim3 grid((N + 127) / 128, (Mr + 127) / 128);
    k_gemm<<<grid, 256>>>(A, W, C, bias, Mr, N, K, lda, ldw, ldc, epi);
}

extern "C" void kernel_launch(void* const* d_in, const int* in_sizes, int n_in,
                              void* d_out, int out_size) {
    const float* x       = (const float*)d_in[0];
    const int*   lengths = (const int*)  d_in[1];
    const float* ln0_g   = (const float*)d_in[2];
    const float* ln0_b   = (const float*)d_in[3];
    const float* ln1_g   = (const float*)d_in[4];
    const float* ln1_b   = (const float*)d_in[5];
    const float* in_w    = (const float*)d_in[6];
    const float* conv_w  = (const float*)d_in[7];
    const float* conv_b  = (const float*)d_in[8];
    const float* xp_w    = (const float*)d_in[9];
    const float* dt_w    = (const float*)d_in[10];
    const float* dt_b    = (const float*)d_in[11];
    const float* A_log   = (const float*)d_in[12];
    const float* D_skip  = (const float*)d_in[13];
    const float* out_w   = (const float*)d_in[14];
    const float* ln2_g   = (const float*)d_in[15];
    const float* ln2_b   = (const float*)d_in[16];
    const float* f1_w    = (const float*)d_in[17];
    const float* f1_b    = (const float*)d_in[18];
    const float* f2_w    = (const float*)d_in[19];
    const float* f2_b    = (const float*)d_in[20];

    float *pX, *pXn, *pXz, *pXc, *pXd, *pDt, *pY, *pF, *pP, *pS, *pI;
    cudaGetSymbolAddress((void**)&pX,  g_X);
    cudaGetSymbolAddress((void**)&pXn, g_Xn);
    cudaGetSymbolAddress((void**)&pXz, g_xz);
    cudaGetSymbolAddress((void**)&pXc, g_xc);
    cudaGetSymbolAddress((void**)&pXd, g_xd);
    cudaGetSymbolAddress((void**)&pDt, g_dt);
    cudaGetSymbolAddress((void**)&pY,  g_ym);
    cudaGetSymbolAddress((void**)&pF,  g_ffn);
    cudaGetSymbolAddress((void**)&pP,  g_cP);
    cudaGetSymbolAddress((void**)&pS,  g_cS);
    cudaGetSymbolAddress((void**)&pI,  g_cI);

    // x + positional encoding
    k_add_pe<<<(MROWS * DM) / 256, 256>>>(x, pX);
    // layer-0 pre-norm (in place)
    k_ln<<<MROWS, 256>>>(pX, pX, ln0_g, ln0_b);

    for (int i = 0; i < 4; i++) {
        // --- Mamba block ---
        k_ln<<<MROWS, 256>>>(pX, pXn, ln1_g + i * DM, ln1_b + i * DM);
        launch_gemm(pXn, in_w + (size_t)i * 2 * DI * DM, pXz, nullptr,
                    MROWS, 2 * DI, DM, DM, DM, 2 * DI, 0);
        k_conv<<<(MROWS * DI) / 256, 256>>>(pXz, conv_w + (size_t)i * DI * 4,
                                            conv_b + (size_t)i * DI, pXc);
        launch_gemm(pXc, xp_w + (size_t)i * 96 * DI, pXd, nullptr,
                    MROWS, 96, DI, DI, DI, 96, 0);
        launch_gemm(pXd, dt_w + (size_t)i * DI * DTR, pDt, dt_b + (size_t)i * DI,
                    MROWS, DI, DTR, 96, DTR, DI, 5);
        dim3 sg(DI / 256, NC, BB);
        k_scanA<<<sg, 256>>>(pDt, pXc, pXd, A_log + (size_t)i * DI * DS_, pP, pS);
        k_scanB<<<(BB * DI) / 256, 256>>>(pP, pS, pI);
        k_scanC<<<sg, 256>>>(pDt, pXc, pXd, pXz, A_log + (size_t)i * DI * DS_,
                             D_skip + (size_t)i * DI, pI, pY);
        launch_gemm(pY, out_w + (size_t)i * DM * DI, pX, nullptr,
                    MROWS, DM, DI, DI, DI, DM, 3);   // residual add
        // --- FFN block ---
        k_ln<<<MROWS, 256>>>(pX, pXn, ln2_g + i * DM, ln2_b + i * DM);
        launch_gemm(pXn, f1_w + (size_t)i * FFND * DM, pF, f1_b + (size_t)i * FFND,
                    MROWS, FFND, DM, DM, DM, FFND, 2); // gelu
        launch_gemm(pF, f2_w + (size_t)i * DM * FFND, pX, f2_b + (size_t)i * DM,
                    MROWS, DM, FFND, FFND, FFND, DM, 4); // residual + bias
        k_mask<<<(MROWS * DM) / 256, 256>>>(pX, lengths,
                                            (i == 3) ? (float*)d_out : nullptr);
    }
}

// round 3
// speedup vs baseline: 1.8007x; 1.8007x over previous
#include <cuda_runtime.h>
#include <stdint.h>
#include <math.h>

#define BB    4
#define TSEQ  2048
#define DM    1024
#define DI    2048
#define DS_   16
#define DTR   64
#define FFND  3584
#define MROWS (BB*TSEQ)   // 8192
#define NC    64          // scan chunks
#define CL    32          // chunk length (NC*CL == TSEQ)

// ---------------- static device scratch (no allocations allowed) ----------
__device__ float g_X  [MROWS*DM];        // residual stream
__device__ float g_Xn [MROWS*DM];        // layernorm output
__device__ float g_xz [MROWS*2*DI];      // in_proj output
__device__ float g_xc [MROWS*DI];        // conv+silu output
__device__ float g_xd [MROWS*96];        // x_proj output (dt|B|C)
__device__ float g_dt [MROWS*DI];        // softplus(dt)
__device__ float g_ym [MROWS*DI];        // gated scan output
__device__ float g_ffn[MROWS*FFND];      // ffn hidden
__device__ float g_cP [BB*NC*DI*DS_];    // chunk transition products
__device__ float g_cS [BB*NC*DI*DS_];    // chunk partial states
__device__ float g_cI [BB*NC*DI*DS_];    // chunk incoming states

// ---------------- positional encoding + input copy ------------------------
__global__ void k_add_pe(const float* __restrict__ xin, float* __restrict__ X) {
    int idx = blockIdx.x * 256 + threadIdx.x;      // over MROWS*DM
    int d = idx & (DM - 1);
    int m = idx >> 10;
    int t = m & (TSEQ - 1);
    int p2 = d & ~1;
    float freq = expf((float)p2 * (-9.210340371976184f / (float)DM));
    float ang = (float)t * freq;
    float pe = (d & 1) ? cosf(ang) : sinf(ang);
    X[idx] = xin[idx] + pe;
}

// ---------------- layernorm (1024 cols, 256 thr, 1 float4/thr) ------------
__device__ __forceinline__ float blockReduce(float v, float* sh) {
    int lane = threadIdx.x & 31, wid = threadIdx.x >> 5;
    #pragma unroll
    for (int o = 16; o > 0; o >>= 1) v += __shfl_down_sync(0xffffffffu, v, o);
    if (lane == 0) sh[wid] = v;
    __syncthreads();
    if (threadIdx.x == 0) {
        float s = 0.f;
        #pragma unroll
        for (int i = 0; i < 8; i++) s += sh[i];
        sh[32] = s;
    }
    __syncthreads();
    float r = sh[32];
    __syncthreads();
    return r;
}

__global__ __launch_bounds__(256) void k_ln(const float* __restrict__ in,
                                            float* __restrict__ out,
                                            const float* __restrict__ g,
                                            const float* __restrict__ b) {
    __shared__ float sh[33];
    int row = blockIdx.x;
    float4 v = ((const float4*)(in + (size_t)row * DM))[threadIdx.x];
    float mean = blockReduce(v.x + v.y + v.z + v.w, sh) * (1.0f / DM);
    float dx = v.x - mean, dy = v.y - mean, dz = v.z - mean, dw = v.w - mean;
    float var = blockReduce(dx*dx + dy*dy + dz*dz + dw*dw, sh) * (1.0f / DM);
    float rstd = rsqrtf(var + 1e-5f);
    int c = threadIdx.x * 4;
    float4 o;
    o.x = dx * rstd * g[c + 0] + b[c + 0];
    o.y = dy * rstd * g[c + 1] + b[c + 1];
    o.z = dz * rstd * g[c + 2] + b[c + 2];
    o.w = dw * rstd * g[c + 3] + b[c + 3];
    ((float4*)(out + (size_t)row * DM))[threadIdx.x] = o;
}

// ---------------- tf32 tensor-core GEMM -----------------------------------
// C[m,n] = sum_k A[m,k] * W[n,k]
// epi: 0:C=acc 1:+bias 2:gelu(acc+bias) 3:C+=acc 4:C+=acc+bias 5:softplus(acc+bias)
#define GBK   16
#define GPAD  20   // smem row stride (floats) -> conflict-free fragment loads

__device__ __forceinline__ uint32_t f2tf32(float f) {
    uint32_t r;
    asm("cvt.rna.tf32.f32 %0, %1;" : "=r"(r) : "f"(f));
    return r;
}
__device__ __forceinline__ void cpasync16(uint32_t dst, const void* src) {
    asm volatile("cp.async.ca.shared.global [%0], [%1], 16;" :: "r"(dst), "l"(src));
}
__device__ __forceinline__ void mma_tf32(float c[4], const uint32_t a[4], const uint32_t b[2]) {
    asm volatile(
        "mma.sync.aligned.m16n8k8.row.col.f32.tf32.tf32.f32 "
        "{%0,%1,%2,%3}, {%4,%5,%6,%7}, {%8,%9}, {%0,%1,%2,%3};"
        : "+f"(c[0]), "+f"(c[1]), "+f"(c[2]), "+f"(c[3])
        : "r"(a[0]), "r"(a[1]), "r"(a[2]), "r"(a[3]), "r"(b[0]), "r"(b[1]));
}

__global__ __launch_bounds__(128, 2) void k_gemm_tc(
    const float* __restrict__ A, const float* __restrict__ W,
    float* __restrict__ C, const float* __restrict__ bias,
    int Mr, int N, int K, int lda, int ldw, int ldc, int epi) {
    __shared__ float As[2][128 * GPAD];
    __shared__ float Bs[2][128 * GPAD];
    const int tid = threadIdx.x;
    const int lane = tid & 31;
    const int wid = tid >> 5;
    const int wm = wid & 1, wn = wid >> 1;       // 2x2 warps, 64x64 each
    const int g = lane >> 2, tig = lane & 3;
    const int bM = blockIdx.y * 128, bN = blockIdx.x * 128;

    int arow = bM + tid; if (arow >= Mr) arow = Mr - 1;
    int wrow = bN + tid; if (wrow >= N)  wrow = N - 1;
    const float* Ag = A + (size_t)arow * lda;
    const float* Wg = W + (size_t)wrow * ldw;

    const uint32_t sA0 = (uint32_t)__cvta_generic_to_shared(&As[0][0]);
    const uint32_t sB0 = (uint32_t)__cvta_generic_to_shared(&Bs[0][0]);
    const uint32_t BUFB = 128 * GPAD * 4;
    const uint32_t dstOff = (uint32_t)tid * GPAD * 4;

    float acc[4][8][4];
    #pragma unroll
    for (int i = 0; i < 4; i++)
        #pragma unroll
        for (int j = 0; j < 8; j++)
            #pragma unroll
            for (int q = 0; q < 4; q++) acc[i][j][q] = 0.f;

    const int KT = K / GBK;
    // prologue: tile 0 -> buf 0
    #pragma unroll
    for (int c = 0; c < 4; c++) {
        cpasync16(sA0 + dstOff + c * 16, Ag + c * 4);
        cpasync16(sB0 + dstOff + c * 16, Wg + c * 4);
    }
    asm volatile("cp.async.commit_group;");

    for (int kt = 0; kt < KT; kt++) {
        const int buf = kt & 1;
        if (kt + 1 < KT) {
            const int nb = buf ^ 1;
            const float* a = Ag + (kt + 1) * GBK;
            const float* w = Wg + (kt + 1) * GBK;
            #pragma unroll
            for (int c = 0; c < 4; c++) {
                cpasync16(sA0 + nb * BUFB + dstOff + c * 16, a + c * 4);
                cpasync16(sB0 + nb * BUFB + dstOff + c * 16, w + c * 4);
            }
            asm volatile("cp.async.commit_group;");
            asm volatile("cp.async.wait_group 1;");
        } else {
            asm volatile("cp.async.wait_group 0;");
        }
        __syncthreads();

        const float* as = &As[buf][0];
        const float* bs = &Bs[buf][0];
        #pragma unroll
        for (int ks = 0; ks < 2; ks++) {
            const int kk = ks * 8 + tig;
            uint32_t af[4][4], bf[8][2];
            #pragma unroll
            for (int i = 0; i < 4; i++) {
                const int r = wm * 64 + i * 16 + g;
                af[i][0] = f2tf32(as[r * GPAD + kk]);
                af[i][1] = f2tf32(as[(r + 8) * GPAD + kk]);
                af[i][2] = f2tf32(as[r * GPAD + kk + 4]);
                af[i][3] = f2tf32(as[(r + 8) * GPAD + kk + 4]);
            }
            #pragma unroll
            for (int j = 0; j < 8; j++) {
                const int cn = wn * 64 + j * 8 + g;
                bf[j][0] = f2tf32(bs[cn * GPAD + kk]);
                bf[j][1] = f2tf32(bs[cn * GPAD + kk + 4]);
            }
            #pragma unroll
            for (int i = 0; i < 4; i++)
                #pragma unroll
                for (int j = 0; j < 8; j++)
                    mma_tf32(acc[i][j], af[i], bf[j]);
        }
        __syncthreads();
    }

    // epilogue
    #pragma unroll
    for (int i = 0; i < 4; i++) {
        const int r0 = bM + wm * 64 + i * 16 + g;
        #pragma unroll
        for (int j = 0; j < 8; j++) {
            const int cn = bN + wn * 64 + j * 8 + tig * 2;
            #pragma unroll
            for (int q = 0; q < 4; q++) {
                const int r = r0 + (q >> 1) * 8;
                const int c = cn + (q & 1);
                if (r >= Mr || c >= N) continue;
                float v = acc[i][j][q];
                float* cp = C + (size_t)r * ldc + c;
                if (epi == 0) { *cp = v; }
                else if (epi == 1) { *cp = v + bias[c]; }
                else if (epi == 2) {
                    float u = v + bias[c];
                    *cp = 0.5f * u * (1.0f + erff(u * 0.70710678118654752f));
                } else if (epi == 3) { *cp = *cp + v; }
                else if (epi == 4) { *cp = *cp + v + bias[c]; }
                else {
                    float u = v + bias[c];
                    *cp = (u > 20.f) ? u : log1pf(expf(u));
                }
            }
        }
    }
}

// ---------------- causal depthwise conv (k=4) + silu ----------------------
__global__ void k_conv(const float* __restrict__ xz, const float* __restrict__ cw,
                       const float* __restrict__ cb, float* __restrict__ xc) {
    int idx = blockIdx.x * 256 + threadIdx.x;   // over MROWS*DI
    int d = idx & (DI - 1);
    int m = idx >> 11;
    int t = m & (TSEQ - 1);
    float acc = cb[d];
    #pragma unroll
    for (int k = 0; k < 4; k++) {
        int tt = t + k - 3;
        if (tt >= 0) acc += xz[(size_t)(m + k - 3) * (2 * DI) + d] * cw[d * 4 + k];
    }
    float sg = 1.0f / (1.0f + expf(-acc));
    xc[idx] = acc * sg;
}

// ---------------- scan pass A: per-chunk transition + partial state -------
__global__ __launch_bounds__(256) void k_scanA(
    const float* __restrict__ dt, const float* __restrict__ xc,
    const float* __restrict__ xd, const float* __restrict__ Alog,
    float* __restrict__ gP, float* __restrict__ gS) {
    __shared__ float shB[CL][DS_];
    int b = blockIdx.z, c = blockIdx.y;
    int d = blockIdx.x * 256 + threadIdx.x;
    int mbase = b * TSEQ + c * CL;
    for (int idx = threadIdx.x; idx < CL * DS_; idx += 256) {
        int t = idx >> 4, col = idx & 15;
        shB[t][col] = xd[(size_t)(mbase + t) * 96 + 64 + col];
    }
    __syncthreads();
    float r[DS_];
    bool fast = true;
    #pragma unroll
    for (int n = 0; n < DS_; n++) {
        r[n] = expf(Alog[(size_t)d * DS_ + n]);
        fast = fast && (fabsf(r[n] - (float)(n + 1)) < 1e-3f * (float)(n + 1));
    }
    float P[DS_], S[DS_];
    #pragma unroll
    for (int n = 0; n < DS_; n++) { P[n] = 1.f; S[n] = 0.f; }
    for (int t = 0; t < CL; t++) {
        int m = mbase + t;
        float dv = dt[(size_t)m * DI + d];
        float xv = xc[(size_t)m * DI + d];
        float u = xv * dv;
        float dA[DS_];
        if (fast) {
            float e = expf(-dv);
            float p = 1.f;
            #pragma unroll
            for (int n = 0; n < DS_; n++) { p *= e; dA[n] = p; }
        } else {
            #pragma unroll
            for (int n = 0; n < DS_; n++) dA[n] = expf(-dv * r[n]);
        }
        #pragma unroll
        for (int n = 0; n < DS_; n++) {
            S[n] = S[n] * dA[n] + u * shB[t][n];
            P[n] *= dA[n];
        }
    }
    size_t base = (((size_t)b * NC + c) * DI + d) * DS_;
    #pragma unroll
    for (int n = 0; n < DS_; n += 4) {
        *(float4*)(gP + base + n) = make_float4(P[n], P[n+1], P[n+2], P[n+3]);
        *(float4*)(gS + base + n) = make_float4(S[n], S[n+1], S[n+2], S[n+3]);
    }
}

// ---------------- scan pass B: sequential chunk combine -------------------
__global__ void k_scanB(const float* __restrict__ gP, const float* __restrict__ gS,
                        float* __restrict__ gI) {
    int idx = blockIdx.x * 256 + threadIdx.x;   // b*DI + d, 8192 total
    int b = idx >> 11, d = idx & (DI - 1);
    float s[DS_];
    #pragma unroll
    for (int n = 0; n < DS_; n++) s[n] = 0.f;
    for (int c = 0; c < NC; c++) {
        size_t base = (((size_t)b * NC + c) * DI + d) * DS_;
        #pragma unroll
        for (int n = 0; n < DS_; n += 4)
            *(float4*)(gI + base + n) = make_float4(s[n], s[n+1], s[n+2], s[n+3]);
        #pragma unroll
        for (int n = 0; n < DS_; n += 4) {
            float4 P = *(const float4*)(gP + base + n);
            float4 S = *(const float4*)(gS + base + n);
            s[n+0] = s[n+0] * P.x + S.x;
            s[n+1] = s[n+1] * P.y + S.y;
            s[n+2] = s[n+2] * P.z + S.z;
            s[n+3] = s[n+3] * P.w + S.w;
        }
    }
}

// ---------------- scan pass C: replay with init state, emit gated output --
__global__ __launch_bounds__(256) void k_scanC(
    const float* __restrict__ dt, const float* __restrict__ xc,
    const float* __restrict__ xd, const float* __restrict__ xz,
    const float* __restrict__ Alog, const float* __restrict__ Dsk,
    const float* __restrict__ gI, float* __restrict__ ym) {
    __shared__ float shB[CL][DS_];
    __shared__ float shC[CL][DS_];
    int b = blockIdx.z, c = blockIdx.y;
    int d = blockIdx.x * 256 + threadIdx.x;
    int mbase = b * TSEQ + c * CL;
    for (int idx = threadIdx.x; idx < CL * 32; idx += 256) {
        int t = idx >> 5, col = idx & 31;
        float v = xd[(size_t)(mbase + t) * 96 + 64 + col];
        if (col < 16) shB[t][col] = v;
        else shC[t][col - 16] = v;
    }
    __syncthreads();
    float r[DS_];
    bool fast = true;
    #pragma unroll
    for (int n = 0; n < DS_; n++) {
        r[n] = expf(Alog[(size_t)d * DS_ + n]);
        fast = fast && (fabsf(r[n] - (float)(n + 1)) < 1e-3f * (float)(n + 1));
    }
    float dskip = Dsk[d];
    float s[DS_];
    size_t base = (((size_t)b * NC + c) * DI + d) * DS_;
    #pragma unroll
    for (int n = 0; n < DS_; n += 4) {
        float4 v = *(const float4*)(gI + base + n);
        s[n+0] = v.x; s[n+1] = v.y; s[n+2] = v.z; s[n+3] = v.w;
    }
    for (int t = 0; t < CL; t++) {
        int m = mbase + t;
        float dv = dt[(size_t)m * DI + d];
        float xv = xc[(size_t)m * DI + d];
        float u = xv * dv;
        float dA[DS_];
        if (fast) {
            float e = expf(-dv);
            float p = 1.f;
            #pragma unroll
            for (int n = 0; n < DS_; n++) { p *= e; dA[n] = p; }
        } else {
            #pragma unroll
            for (int n = 0; n < DS_; n++) dA[n] = expf(-dv * r[n]);
        }
        float y = 0.f;
        #pragma unroll
        for (int n = 0; n < DS_; n++) {
            s[n] = s[n] * dA[n] + u * shB[t][n];
            y += s[n] * shC[t][n];
        }
        float z = xz[(size_t)m * (2 * DI) + DI + d];
        float sg = 1.0f / (1.0f + expf(-z));
        ym[(size_t)m * DI + d] = (y + dskip * xv) * (z * sg);
    }
}

// ---------------- mask (+ optional write to output) -----------------------
__global__ void k_mask(float* __restrict__ X, const int* __restrict__ len,
                       float* __restrict__ out2) {
    int idx = blockIdx.x * 256 + threadIdx.x;   // over MROWS*DM
    int m = idx >> 10;
    int b = m >> 11;
    int t = m & (TSEQ - 1);
    float v = X[idx];
    v = (t < len[b]) ? v : 0.f;
    X[idx] = v;
    if (out2) out2[idx] = v;
}

// ---------------- host orchestration --------------------------------------
static void launch_gemm(const float* A, const float* W, float* C, const float* bias,
                        int Mr, int N, int K, int lda, int ldw, int ldc, int epi) {
    dim3 grid((N + 127) / 128, (Mr + 127) / 128);
    k_gemm_tc<<<grid, 128>>>(A, W, C, bias, Mr, N, K, lda, ldw, ldc, epi);
}

extern "C" void kernel_launch(void* const* d_in, const int* in_sizes, int n_in,
                              void* d_out, int out_size) {
    const float* x       = (const float*)d_in[0];
    const int*   lengths = (const int*)  d_in[1];
    const float* ln0_g   = (const float*)d_in[2];
    const float* ln0_b   = (const float*)d_in[3];
    const float* ln1_g   = (const float*)d_in[4];
    const float* ln1_b   = (const float*)d_in[5];
    const float* in_w    = (const float*)d_in[6];
    const float* conv_w  = (const float*)d_in[7];
    const float* conv_b  = (const float*)d_in[8];
    const float* xp_w    = (const float*)d_in[9];
    const float* dt_w    = (const float*)d_in[10];
    const float* dt_b    = (const float*)d_in[11];
    const float* A_log   = (const float*)d_in[12];
    const float* D_skip  = (const float*)d_in[13];
    const float* out_w   = (const float*)d_in[14];
    const float* ln2_g   = (const float*)d_in[15];
    const float* ln2_b   = (const float*)d_in[16];
    const float* f1_w    = (const float*)d_in[17];
    const float* f1_b    = (const float*)d_in[18];
    const float* f2_w    = (const float*)d_in[19];
    const float* f2_b    = (const float*)d_in[20];

    float *pX, *pXn, *pXz, *pXc, *pXd, *pDt, *pY, *pF, *pP, *pS, *pI;
    cudaGetSymbolAddress((void**)&pX,  g_X);
    cudaGetSymbolAddress((void**)&pXn, g_Xn);
    cudaGetSymbolAddress((void**)&pXz, g_xz);
    cudaGetSymbolAddress((void**)&pXc, g_xc);
    cudaGetSymbolAddress((void**)&pXd, g_xd);
    cudaGetSymbolAddress((void**)&pDt, g_dt);
    cudaGetSymbolAddress((void**)&pY,  g_ym);
    cudaGetSymbolAddress((void**)&pF,  g_ffn);
    cudaGetSymbolAddress((void**)&pP,  g_cP);
    cudaGetSymbolAddress((void**)&pS,  g_cS);
    cudaGetSymbolAddress((void**)&pI,  g_cI);

    // x + positional encoding
    k_add_pe<<<(MROWS * DM) / 256, 256>>>(x, pX);
    // layer-0 pre-norm (in place)
    k_ln<<<MROWS, 256>>>(pX, pX, ln0_g, ln0_b);

    for (int i = 0; i < 4; i++) {
        // --- Mamba block ---
        k_ln<<<MROWS, 256>>>(pX, pXn, ln1_g + i * DM, ln1_b + i * DM);
        launch_gemm(pXn, in_w + (size_t)i * 2 * DI * DM, pXz, nullptr,
                    MROWS, 2 * DI, DM, DM, DM, 2 * DI, 0);
        k_conv<<<(MROWS * DI) / 256, 256>>>(pXz, conv_w + (size_t)i * DI * 4,
                                            conv_b + (size_t)i * DI, pXc);
        launch_gemm(pXc, xp_w + (size_t)i * 96 * DI, pXd, nullptr,
                    MROWS, 96, DI, DI, DI, 96, 0);
        launch_gemm(pXd, dt_w + (size_t)i * DI * DTR, pDt, dt_b + (size_t)i * DI,
                    MROWS, DI, DTR, 96, DTR, DI, 5);
        dim3 sg(DI / 256, NC, BB);
        k_scanA<<<sg, 256>>>(pDt, pXc, pXd, A_log + (size_t)i * DI * DS_, pP, pS);
        k_scanB<<<(BB * DI) / 256, 256>>>(pP, pS, pI);
        k_scanC<<<sg, 256>>>(pDt, pXc, pXd, pXz, A_log + (size_t)i * DI * DS_,
                             D_skip + (size_t)i * DI, pI, pY);
        launch_gemm(pY, out_w + (size_t)i * DM * DI, pX, nullptr,
                    MROWS, DM, DI, DI, DI, DM, 3);   // residual add
        // --- FFN block ---
        k_ln<<<MROWS, 256>>>(pX, pXn, ln2_g + i * DM, ln2_b + i * DM);
        launch_gemm(pXn, f1_w + (size_t)i * FFND * DM, pF, f1_b + (size_t)i * FFND,
                    MROWS, FFND, DM, DM, DM, FFND, 2); // gelu
        launch_gemm(pF, f2_w + (size_t)i * DM * FFND, pX, f2_b + (size_t)i * DM,
                    MROWS, DM, FFND, FFND, FFND, DM, 4); // residual + bias
        k_mask<<<(MROWS * DM) / 256, 256>>>(pX, lengths,
                                            (i == 3) ? (float*)d_out : nullptr);
    }
}

// round 4
// speedup vs baseline: 2.3161x; 1.2862x over previous
#include <cuda_runtime.h>
#include <stdint.h>
#include <math.h>

#define BB    4
#define TSEQ  2048
#define DM    1024
#define DI    2048
#define DS_   16
#define DTR   64
#define FFND  3584
#define MROWS (BB*TSEQ)   // 8192
#define NC    64          // scan chunks
#define CL    32          // chunk length (NC*CL == TSEQ)

// ---------------- static device scratch (no allocations allowed) ----------
__device__ float g_X  [MROWS*DM];        // residual stream
__device__ float g_Xn [MROWS*DM];        // layernorm output
__device__ float g_xz [MROWS*2*DI];      // in_proj output
__device__ float g_xc [MROWS*DI];        // conv+silu output
__device__ float g_xd [MROWS*96];        // x_proj output (dt|B|C)
__device__ float g_dt [MROWS*DI];        // softplus(dt)
__device__ float g_ym [MROWS*DI];        // gated scan output
__device__ float g_ffn[MROWS*FFND];      // ffn hidden
__device__ float g_cP [BB*NC*DI*DS_];    // chunk transition products
__device__ float g_cS [BB*NC*DI*DS_];    // chunk partial states
__device__ float g_cI [BB*NC*DI*DS_];    // chunk incoming states

// ---------------- positional encoding + input copy ------------------------
__global__ void k_add_pe(const float* __restrict__ xin, float* __restrict__ X) {
    int idx = blockIdx.x * 256 + threadIdx.x;      // over MROWS*DM
    int d = idx & (DM - 1);
    int m = idx >> 10;
    int t = m & (TSEQ - 1);
    int p2 = d & ~1;
    float freq = expf((float)p2 * (-9.210340371976184f / (float)DM));
    float ang = (float)t * freq;
    float pe = (d & 1) ? cosf(ang) : sinf(ang);
    X[idx] = xin[idx] + pe;
}

// ---------------- layernorm (1024 cols, 256 thr, 1 float4/thr) ------------
__device__ __forceinline__ float blockReduce(float v, float* sh) {
    int lane = threadIdx.x & 31, wid = threadIdx.x >> 5;
    #pragma unroll
    for (int o = 16; o > 0; o >>= 1) v += __shfl_down_sync(0xffffffffu, v, o);
    if (lane == 0) sh[wid] = v;
    __syncthreads();
    if (threadIdx.x == 0) {
        float s = 0.f;
        #pragma unroll
        for (int i = 0; i < 8; i++) s += sh[i];
        sh[32] = s;
    }
    __syncthreads();
    float r = sh[32];
    __syncthreads();
    return r;
}

__global__ __launch_bounds__(256) void k_ln(const float* __restrict__ in,
                                            float* __restrict__ out,
                                            const float* __restrict__ g,
                                            const float* __restrict__ b) {
    __shared__ float sh[33];
    int row = blockIdx.x;
    float4 v = ((const float4*)(in + (size_t)row * DM))[threadIdx.x];
    float mean = blockReduce(v.x + v.y + v.z + v.w, sh) * (1.0f / DM);
    float dx = v.x - mean, dy = v.y - mean, dz = v.z - mean, dw = v.w - mean;
    float var = blockReduce(dx*dx + dy*dy + dz*dz + dw*dw, sh) * (1.0f / DM);
    float rstd = rsqrtf(var + 1e-5f);
    int c = threadIdx.x * 4;
    float4 o;
    o.x = dx * rstd * g[c + 0] + b[c + 0];
    o.y = dy * rstd * g[c + 1] + b[c + 1];
    o.z = dz * rstd * g[c + 2] + b[c + 2];
    o.w = dw * rstd * g[c + 3] + b[c + 3];
    ((float4*)(out + (size_t)row * DM))[threadIdx.x] = o;
}

// ---------------- tf32 tensor-core GEMM -----------------------------------
// C[m,n] = sum_k A[m,k] * W[n,k]
// 128x128 block, 256 threads (8 warps, 2x4), warp tile 64x32
// epi: 0:C=acc 1:+bias 2:gelu(acc+bias) 3:C+=acc 4:C+=acc+bias 5:softplus(acc+bias)
#define GBK   16
#define GPAD  20   // smem row stride (floats) -> conflict-free fragment loads

__device__ __forceinline__ uint32_t f2tf32(float f) {
    uint32_t r;
    asm("cvt.rna.tf32.f32 %0, %1;" : "=r"(r) : "f"(f));
    return r;
}
__device__ __forceinline__ void cpasync16(uint32_t dst, const void* src) {
    asm volatile("cp.async.ca.shared.global [%0], [%1], 16;" :: "r"(dst), "l"(src));
}
__device__ __forceinline__ void mma_tf32(float c[4], const uint32_t a[4], const uint32_t b[2]) {
    asm volatile(
        "mma.sync.aligned.m16n8k8.row.col.f32.tf32.tf32.f32 "
        "{%0,%1,%2,%3}, {%4,%5,%6,%7}, {%8,%9}, {%0,%1,%2,%3};"
        : "+f"(c[0]), "+f"(c[1]), "+f"(c[2]), "+f"(c[3])
        : "r"(a[0]), "r"(a[1]), "r"(a[2]), "r"(a[3]), "r"(b[0]), "r"(b[1]));
}

__global__ __launch_bounds__(256, 2) void k_gemm_tc(
    const float* __restrict__ A, const float* __restrict__ W,
    float* __restrict__ C, const float* __restrict__ bias,
    int Mr, int N, int K, int lda, int ldw, int ldc, int epi) {
    __shared__ float As[2][128 * GPAD];
    __shared__ float Bs[2][128 * GPAD];
    const int tid = threadIdx.x;
    const int lane = tid & 31;
    const int wid = tid >> 5;
    const int wm = wid & 1;                      // 2 m-positions (64 rows)
    const int wn = wid >> 1;                     // 4 n-positions (32 cols)
    const int g = lane >> 2, tig = lane & 3;
    const int bM = blockIdx.y * 128, bN = blockIdx.x * 128;

    // loaders: 256 threads, each loads 8 floats (half a 16-float k-row)
    const int lrow = tid >> 1;
    const int lhalf = (tid & 1) << 3;            // 0 or 8
    int arow = bM + lrow; if (arow >= Mr) arow = Mr - 1;
    int wrow = bN + lrow; if (wrow >= N)  wrow = N - 1;
    const float* Ag = A + (size_t)arow * lda + lhalf;
    const float* Wg = W + (size_t)wrow * ldw + lhalf;

    const uint32_t sA0 = (uint32_t)__cvta_generic_to_shared(&As[0][0]);
    const uint32_t sB0 = (uint32_t)__cvta_generic_to_shared(&Bs[0][0]);
    const uint32_t BUFB = 128 * GPAD * 4;
    const uint32_t dstOff = (uint32_t)lrow * GPAD * 4 + (uint32_t)lhalf * 4;

    float acc[4][4][4];
    #pragma unroll
    for (int i = 0; i < 4; i++)
        #pragma unroll
        for (int j = 0; j < 4; j++)
            #pragma unroll
            for (int q = 0; q < 4; q++) acc[i][j][q] = 0.f;

    const int KT = K / GBK;
    // prologue: tile 0 -> buf 0
    #pragma unroll
    for (int c = 0; c < 2; c++) {
        cpasync16(sA0 + dstOff + c * 16, Ag + c * 4);
        cpasync16(sB0 + dstOff + c * 16, Wg + c * 4);
    }
    asm volatile("cp.async.commit_group;");

    for (int kt = 0; kt < KT; kt++) {
        const int buf = kt & 1;
        if (kt + 1 < KT) {
            const int nb = buf ^ 1;
            const float* a = Ag + (kt + 1) * GBK;
            const float* w = Wg + (kt + 1) * GBK;
            #pragma unroll
            for (int c = 0; c < 2; c++) {
                cpasync16(sA0 + nb * BUFB + dstOff + c * 16, a + c * 4);
                cpasync16(sB0 + nb * BUFB + dstOff + c * 16, w + c * 4);
            }
            asm volatile("cp.async.commit_group;");
            asm volatile("cp.async.wait_group 1;");
        } else {
            asm volatile("cp.async.wait_group 0;");
        }
        __syncthreads();

        const float* as = &As[buf][0];
        const float* bs = &Bs[buf][0];
        #pragma unroll
        for (int ks = 0; ks < 2; ks++) {
            const int kk = ks * 8 + tig;
            uint32_t af[4][4], bf[4][2];
            #pragma unroll
            for (int i = 0; i < 4; i++) {
                const int r = wm * 64 + i * 16 + g;
                af[i][0] = f2tf32(as[r * GPAD + kk]);
                af[i][1] = f2tf32(as[(r + 8) * GPAD + kk]);
                af[i][2] = f2tf32(as[r * GPAD + kk + 4]);
                af[i][3] = f2tf32(as[(r + 8) * GPAD + kk + 4]);
            }
            #pragma unroll
            for (int j = 0; j < 4; j++) {
                const int cn = wn * 32 + j * 8 + g;
                bf[j][0] = f2tf32(bs[cn * GPAD + kk]);
                bf[j][1] = f2tf32(bs[cn * GPAD + kk + 4]);
            }
            #pragma unroll
            for (int i = 0; i < 4; i++)
                #pragma unroll
                for (int j = 0; j < 4; j++)
                    mma_tf32(acc[i][j], af[i], bf[j]);
        }
        __syncthreads();
    }

    // epilogue
    #pragma unroll
    for (int i = 0; i < 4; i++) {
        const int r0 = bM + wm * 64 + i * 16 + g;
        #pragma unroll
        for (int j = 0; j < 4; j++) {
            const int cn = bN + wn * 32 + j * 8 + tig * 2;
            #pragma unroll
            for (int q = 0; q < 4; q++) {
                const int r = r0 + (q >> 1) * 8;
                const int c = cn + (q & 1);
                if (r >= Mr || c >= N) continue;
                float v = acc[i][j][q];
                float* cp = C + (size_t)r * ldc + c;
                if (epi == 0) { *cp = v; }
                else if (epi == 1) { *cp = v + bias[c]; }
                else if (epi == 2) {
                    float u = v + bias[c];
                    *cp = 0.5f * u * (1.0f + erff(u * 0.70710678118654752f));
                } else if (epi == 3) { *cp = *cp + v; }
                else if (epi == 4) { *cp = *cp + v + bias[c]; }
                else {
                    float u = v + bias[c];
                    *cp = (u > 20.f) ? u : log1pf(expf(u));
                }
            }
        }
    }
}

// ---------------- causal depthwise conv (k=4) + silu ----------------------
__global__ void k_conv(const float* __restrict__ xz, const float* __restrict__ cw,
                       const float* __restrict__ cb, float* __restrict__ xc) {
    int idx = blockIdx.x * 256 + threadIdx.x;   // over MROWS*DI
    int d = idx & (DI - 1);
    int m = idx >> 11;
    int t = m & (TSEQ - 1);
    float acc = cb[d];
    #pragma unroll
    for (int k = 0; k < 4; k++) {
        int tt = t + k - 3;
        if (tt >= 0) acc += xz[(size_t)(m + k - 3) * (2 * DI) + d] * cw[d * 4 + k];
    }
    float sg = 1.0f / (1.0f + expf(-acc));
    xc[idx] = acc * sg;
}

// ---------------- scan pass A: per-chunk transition + partial state -------
__global__ __launch_bounds__(256) void k_scanA(
    const float* __restrict__ dt, const float* __restrict__ xc,
    const float* __restrict__ xd, const float* __restrict__ Alog,
    float* __restrict__ gP, float* __restrict__ gS) {
    __shared__ float shB[CL][DS_];
    int b = blockIdx.z, c = blockIdx.y;
    int d = blockIdx.x * 256 + threadIdx.x;
    int mbase = b * TSEQ + c * CL;
    for (int idx = threadIdx.x; idx < CL * DS_; idx += 256) {
        int t = idx >> 4, col = idx & 15;
        shB[t][col] = xd[(size_t)(mbase + t) * 96 + 64 + col];
    }
    __syncthreads();
    float r[DS_];
    bool fast = true;
    #pragma unroll
    for (int n = 0; n < DS_; n++) {
        r[n] = expf(Alog[(size_t)d * DS_ + n]);
        fast = fast && (fabsf(r[n] - (float)(n + 1)) < 1e-3f * (float)(n + 1));
    }
    float P[DS_], S[DS_];
    #pragma unroll
    for (int n = 0; n < DS_; n++) { P[n] = 1.f; S[n] = 0.f; }
    for (int t = 0; t < CL; t++) {
        int m = mbase + t;
        float dv = dt[(size_t)m * DI + d];
        float xv = xc[(size_t)m * DI + d];
        float u = xv * dv;
        float dA[DS_];
        if (fast) {
            float e = expf(-dv);
            float p = 1.f;
            #pragma unroll
            for (int n = 0; n < DS_; n++) { p *= e; dA[n] = p; }
        } else {
            #pragma unroll
            for (int n = 0; n < DS_; n++) dA[n] = expf(-dv * r[n]);
        }
        #pragma unroll
        for (int n = 0; n < DS_; n++) {
            S[n] = S[n] * dA[n] + u * shB[t][n];
            P[n] *= dA[n];
        }
    }
    size_t base = (((size_t)b * NC + c) * DI + d) * DS_;
    #pragma unroll
    for (int n = 0; n < DS_; n += 4) {
        *(float4*)(gP + base + n) = make_float4(P[n], P[n+1], P[n+2], P[n+3]);
        *(float4*)(gS + base + n) = make_float4(S[n], S[n+1], S[n+2], S[n+3]);
    }
}

// ---------------- scan pass B: sequential chunk combine -------------------
__global__ void k_scanB(const float* __restrict__ gP, const float* __restrict__ gS,
                        float* __restrict__ gI) {
    int idx = blockIdx.x * 256 + threadIdx.x;   // b*DI + d, 8192 total
    int b = idx >> 11, d = idx & (DI - 1);
    float s[DS_];
    #pragma unroll
    for (int n = 0; n < DS_; n++) s[n] = 0.f;
    for (int c = 0; c < NC; c++) {
        size_t base = (((size_t)b * NC + c) * DI + d) * DS_;
        #pragma unroll
        for (int n = 0; n < DS_; n += 4)
            *(float4*)(gI + base + n) = make_float4(s[n], s[n+1], s[n+2], s[n+3]);
        #pragma unroll
        for (int n = 0; n < DS_; n += 4) {
            float4 P = *(const float4*)(gP + base + n);
            float4 S = *(const float4*)(gS + base + n);
            s[n+0] = s[n+0] * P.x + S.x;
            s[n+1] = s[n+1] * P.y + S.y;
            s[n+2] = s[n+2] * P.z + S.z;
            s[n+3] = s[n+3] * P.w + S.w;
        }
    }
}

// ---------------- scan pass C: replay with init state, emit gated output --
__global__ __launch_bounds__(256) void k_scanC(
    const float* __restrict__ dt, const float* __restrict__ xc,
    const float* __restrict__ xd, const float* __restrict__ xz,
    const float* __restrict__ Alog, const float* __restrict__ Dsk,
    const float* __restrict__ gI, float* __restrict__ ym) {
    __shared__ float shB[CL][DS_];
    __shared__ float shC[CL][DS_];
    int b = blockIdx.z, c = blockIdx.y;
    int d = blockIdx.x * 256 + threadIdx.x;
    int mbase = b * TSEQ + c * CL;
    for (int idx = threadIdx.x; idx < CL * 32; idx += 256) {
        int t = idx >> 5, col = idx & 31;
        float v = xd[(size_t)(mbase + t) * 96 + 64 + col];
        if (col < 16) shB[t][col] = v;
        else shC[t][col - 16] = v;
    }
    __syncthreads();
    float r[DS_];
    bool fast = true;
    #pragma unroll
    for (int n = 0; n < DS_; n++) {
        r[n] = expf(Alog[(size_t)d * DS_ + n]);
        fast = fast && (fabsf(r[n] - (float)(n + 1)) < 1e-3f * (float)(n + 1));
    }
    float dskip = Dsk[d];
    float s[DS_];
    size_t base = (((size_t)b * NC + c) * DI + d) * DS_;
    #pragma unroll
    for (int n = 0; n < DS_; n += 4) {
        float4 v = *(const float4*)(gI + base + n);
        s[n+0] = v.x; s[n+1] = v.y; s[n+2] = v.z; s[n+3] = v.w;
    }
    for (int t = 0; t < CL; t++) {
        int m = mbase + t;
        float dv = dt[(size_t)m * DI + d];
        float xv = xc[(size_t)m * DI + d];
        float u = xv * dv;
        float dA[DS_];
        if (fast) {
            float e = expf(-dv);
            float p = 1.f;
            #pragma unroll
            for (int n = 0; n < DS_; n++) { p *= e; dA[n] = p; }
        } else {
            #pragma unroll
            for (int n = 0; n < DS_; n++) dA[n] = expf(-dv * r[n]);
        }
        float y = 0.f;
        #pragma unroll
        for (int n = 0; n < DS_; n++) {
            s[n] = s[n] * dA[n] + u * shB[t][n];
            y += s[n] * shC[t][n];
        }
        float z = xz[(size_t)m * (2 * DI) + DI + d];
        float sg = 1.0f / (1.0f + expf(-z));
        ym[(size_t)m * DI + d] = (y + dskip * xv) * (z * sg);
    }
}

// ---------------- mask (+ optional write to output) -----------------------
__global__ void k_mask(float* __restrict__ X, const int* __restrict__ len,
                       float* __restrict__ out2) {
    int idx = blockIdx.x * 256 + threadIdx.x;   // over MROWS*DM
    int m = idx >> 10;
    int b = m >> 11;
    int t = m & (TSEQ - 1);
    float v = X[idx];
    v = (t < len[b]) ? v : 0.f;
    X[idx] = v;
    if (out2) out2[idx] = v;
}

// ---------------- host orchestration --------------------------------------
static void launch_gemm(const float* A, const float* W, float* C, const float* bias,
                        int Mr, int N, int K, int lda, int ldw, int ldc, int epi) {
    dim3 grid((N + 127) / 128, (Mr + 127) / 128);
    k_gemm_tc<<<grid, 256>>>(A, W, C, bias, Mr, N, K, lda, ldw, ldc, epi);
}

extern "C" void kernel_launch(void* const* d_in, const int* in_sizes, int n_in,
                              void* d_out, int out_size) {
    const float* x       = (const float*)d_in[0];
    const int*   lengths = (const int*)  d_in[1];
    const float* ln0_g   = (const float*)d_in[2];
    const float* ln0_b   = (const float*)d_in[3];
    const float* ln1_g   = (const float*)d_in[4];
    const float* ln1_b   = (const float*)d_in[5];
    const float* in_w    = (const float*)d_in[6];
    const float* conv_w  = (const float*)d_in[7];
    const float* conv_b  = (const float*)d_in[8];
    const float* xp_w    = (const float*)d_in[9];
    const float* dt_w    = (const float*)d_in[10];
    const float* dt_b    = (const float*)d_in[11];
    const float* A_log   = (const float*)d_in[12];
    const float* D_skip  = (const float*)d_in[13];
    const float* out_w   = (const float*)d_in[14];
    const float* ln2_g   = (const float*)d_in[15];
    const float* ln2_b   = (const float*)d_in[16];
    const float* f1_w    = (const float*)d_in[17];
    const float* f1_b    = (const float*)d_in[18];
    const float* f2_w    = (const float*)d_in[19];
    const float* f2_b    = (const float*)d_in[20];

    float *pX, *pXn, *pXz, *pXc, *pXd, *pDt, *pY, *pF, *pP, *pS, *pI;
    cudaGetSymbolAddress((void**)&pX,  g_X);
    cudaGetSymbolAddress((void**)&pXn, g_Xn);
    cudaGetSymbolAddress((void**)&pXz, g_xz);
    cudaGetSymbolAddress((void**)&pXc, g_xc);
    cudaGetSymbolAddress((void**)&pXd, g_xd);
    cudaGetSymbolAddress((void**)&pDt, g_dt);
    cudaGetSymbolAddress((void**)&pY,  g_ym);
    cudaGetSymbolAddress((void**)&pF,  g_ffn);
    cudaGetSymbolAddress((void**)&pP,  g_cP);
    cudaGetSymbolAddress((void**)&pS,  g_cS);
    cudaGetSymbolAddress((void**)&pI,  g_cI);

    // x + positional encoding
    k_add_pe<<<(MROWS * DM) / 256, 256>>>(x, pX);
    // layer-0 pre-norm (in place)
    k_ln<<<MROWS, 256>>>(pX, pX, ln0_g, ln0_b);

    for (int i = 0; i < 4; i++) {
        // --- Mamba block ---
        k_ln<<<MROWS, 256>>>(pX, pXn, ln1_g + i * DM, ln1_b + i * DM);
        launch_gemm(pXn, in_w + (size_t)i * 2 * DI * DM, pXz, nullptr,
                    MROWS, 2 * DI, DM, DM, DM, 2 * DI, 0);
        k_conv<<<(MROWS * DI) / 256, 256>>>(pXz, conv_w + (size_t)i * DI * 4,
                                            conv_b + (size_t)i * DI, pXc);
        launch_gemm(pXc, xp_w + (size_t)i * 96 * DI, pXd, nullptr,
                    MROWS, 96, DI, DI, DI, 96, 0);
        launch_gemm(pXd, dt_w + (size_t)i * DI * DTR, pDt, dt_b + (size_t)i * DI,
                    MROWS, DI, DTR, 96, DTR, DI, 5);
        dim3 sg(DI / 256, NC, BB);
        k_scanA<<<sg, 256>>>(pDt, pXc, pXd, A_log + (size_t)i * DI * DS_, pP, pS);
        k_scanB<<<(BB * DI) / 256, 256>>>(pP, pS, pI);
        k_scanC<<<sg, 256>>>(pDt, pXc, pXd, pXz, A_log + (size_t)i * DI * DS_,
                             D_skip + (size_t)i * DI, pI, pY);
        launch_gemm(pY, out_w + (size_t)i * DM * DI, pX, nullptr,
                    MROWS, DM, DI, DI, DI, DM, 3);   // residual add
        // --- FFN block ---
        k_ln<<<MROWS, 256>>>(pX, pXn, ln2_g + i * DM, ln2_b + i * DM);
        launch_gemm(pXn, f1_w + (size_t)i * FFND * DM, pF, f1_b + (size_t)i * FFND,
                    MROWS, FFND, DM, DM, DM, FFND, 2); // gelu
        launch_gemm(pF, f2_w + (size_t)i * DM * FFND, pX, f2_b + (size_t)i * DM,
                    MROWS, DM, FFND, FFND, FFND, DM, 4); // residual + bias
        k_mask<<<(MROWS * DM) / 256, 256>>>(pX, lengths,
                                            (i == 3) ? (float*)d_out : nullptr);
    }
}